// round 1
// baseline (speedup 1.0000x reference)
#include <cuda_runtime.h>
#include <stdint.h>

// ============================================================================
// VoxelLayer: two cascaded voxel-grid downsamples.
//   Layer 1: x (16,3,N) -> voxel_x1 (16,3,N/2), voxel 0.05
//   Layer 2: voxel_x1    -> voxel_x2 (16,3,N/4), voxel 0.10
// Strategy: dense histogram over the (small) voxel grid + lin-order compaction
// (== JAX's sorted-lin segment order), then threefry-exact resampling.
// ============================================================================

#define BMAX 16
#define GMAX 10648   // 22^3 upper bound on grid cells per batch (data is U[0,1))

__device__ double   g_sums[(size_t)BMAX * GMAX * 3];
__device__ unsigned g_cnt[BMAX * GMAX];
__device__ float4   g_means[BMAX * GMAX];
__device__ int      g_numvox[BMAX];
__device__ unsigned g_minEnc[BMAX * 3];
__device__ unsigned g_maxEnc[BMAX * 3];

struct KeyArr { unsigned a[BMAX]; unsigned b[BMAX]; };

// ---- JAX threefry2x32 block (rotations + key schedule per jax/_src/prng.py)
__host__ __device__ inline void threefry2x32(unsigned k0, unsigned k1,
                                             unsigned x0, unsigned x1,
                                             unsigned& o0, unsigned& o1) {
  unsigned ks2 = k0 ^ k1 ^ 0x1BD11BDAu;
  x0 += k0; x1 += k1;
#define TFR(r) { x0 += x1; x1 = (x1 << (r)) | (x1 >> (32 - (r))); x1 ^= x0; }
  TFR(13) TFR(15) TFR(26) TFR(6)
  x0 += k1;  x1 += ks2 + 1u;
  TFR(17) TFR(29) TFR(16) TFR(24)
  x0 += ks2; x1 += k0 + 2u;
  TFR(13) TFR(15) TFR(26) TFR(6)
  x0 += k0;  x1 += k1 + 3u;
  TFR(17) TFR(29) TFR(16) TFR(24)
  x0 += k1;  x1 += ks2 + 4u;
  TFR(13) TFR(15) TFR(26) TFR(6)
  x0 += ks2; x1 += k0 + 5u;
#undef TFR
  o0 = x0; o1 = x1;
}

// ---- order-preserving float<->uint encoding for atomicMin/Max
__device__ __forceinline__ unsigned fenc(float f) {
  unsigned u = __float_as_uint(f);
  return (u & 0x80000000u) ? ~u : (u | 0x80000000u);
}
__device__ __forceinline__ float fdec(unsigned e) {
  unsigned u = (e & 0x80000000u) ? (e & 0x7FFFFFFFu) : ~e;
  return __uint_as_float(u);
}

// ---- dims: identical fp path to JAX's max(floor((p-mn)/vox))+1 (monotone)
__device__ __forceinline__ void get_dims(int b, float vox, int& d0, int& d1, int& d2,
                                         float& mn0, float& mn1, float& mn2) {
  mn0 = fdec(g_minEnc[b * 3 + 0]);
  mn1 = fdec(g_minEnc[b * 3 + 1]);
  mn2 = fdec(g_minEnc[b * 3 + 2]);
  float mx0 = fdec(g_maxEnc[b * 3 + 0]);
  float mx1 = fdec(g_maxEnc[b * 3 + 1]);
  float mx2 = fdec(g_maxEnc[b * 3 + 2]);
  d0 = (int)floorf(__fdiv_rn(__fsub_rn(mx0, mn0), vox)) + 1;
  d1 = (int)floorf(__fdiv_rn(__fsub_rn(mx1, mn1), vox)) + 1;
  d2 = (int)floorf(__fdiv_rn(__fsub_rn(mx2, mn2), vox)) + 1;
}

// ============================================================================
__global__ void k_init(int B) {
  int total = B * GMAX;
  int stride = gridDim.x * blockDim.x;
  for (int i = blockIdx.x * blockDim.x + threadIdx.x; i < total; i += stride) {
    g_cnt[i] = 0u;
    g_sums[(size_t)i * 3 + 0] = 0.0;
    g_sums[(size_t)i * 3 + 1] = 0.0;
    g_sums[(size_t)i * 3 + 2] = 0.0;
  }
  int t = blockIdx.x * blockDim.x + threadIdx.x;
  if (t < B * 3) { g_minEnc[t] = 0xFFFFFFFFu; g_maxEnc[t] = 0u; }
}

__global__ void k_minmax(const float* __restrict__ x, int N) {
  int row = blockIdx.y;  // b*3 + d
  const float* p = x + (size_t)row * N;
  unsigned mn = 0xFFFFFFFFu, mx = 0u;
  for (int i = blockIdx.x * blockDim.x + threadIdx.x; i < N;
       i += gridDim.x * blockDim.x) {
    unsigned e = fenc(p[i]);
    mn = min(mn, e); mx = max(mx, e);
  }
#pragma unroll
  for (int o = 16; o; o >>= 1) {
    mn = min(mn, __shfl_down_sync(0xffffffffu, mn, o));
    mx = max(mx, __shfl_down_sync(0xffffffffu, mx, o));
  }
  __shared__ unsigned smn[32], smx[32];
  int lane = threadIdx.x & 31, warp = threadIdx.x >> 5;
  if (lane == 0) { smn[warp] = mn; smx[warp] = mx; }
  __syncthreads();
  if (warp == 0) {
    int nw = blockDim.x >> 5;
    mn = (lane < nw) ? smn[lane] : 0xFFFFFFFFu;
    mx = (lane < nw) ? smx[lane] : 0u;
#pragma unroll
    for (int o = 16; o; o >>= 1) {
      mn = min(mn, __shfl_down_sync(0xffffffffu, mn, o));
      mx = max(mx, __shfl_down_sync(0xffffffffu, mx, o));
    }
    if (lane == 0) { atomicMin(&g_minEnc[row], mn); atomicMax(&g_maxEnc[row], mx); }
  }
}

__global__ void k_accum(const float* __restrict__ x, int N, float vox) {
  int b = blockIdx.y;
  int i = blockIdx.x * blockDim.x + threadIdx.x;
  if (i >= N) return;
  int d0, d1, d2; float mn0, mn1, mn2;
  get_dims(b, vox, d0, d1, d2, mn0, mn1, mn2);
  const float* base = x + (size_t)b * 3 * N;
  float p0 = base[i];
  float p1 = base[(size_t)N + i];
  float p2 = base[(size_t)2 * N + i];
  int v0 = (int)floorf(__fdiv_rn(__fsub_rn(p0, mn0), vox));
  int v1 = (int)floorf(__fdiv_rn(__fsub_rn(p1, mn1), vox));
  int v2 = (int)floorf(__fdiv_rn(__fsub_rn(p2, mn2), vox));
  int lin = (v0 * d1 + v1) * d2 + v2;
  if (lin < 0) lin = 0;
  if (lin > GMAX - 1) lin = GMAX - 1;  // safety only; never hit for U[0,1) data
  double* s = &g_sums[((size_t)b * GMAX + lin) * 3];
  atomicAdd(s + 0, (double)p0);
  atomicAdd(s + 1, (double)p1);
  atomicAdd(s + 2, (double)p2);
  atomicAdd(&g_cnt[b * GMAX + lin], 1u);
}

// one block per batch: scan occupied cells in lin order -> compact means
__global__ void k_compact(float vox) {
  int b = blockIdx.x;
  int d0, d1, d2; float mn0, mn1, mn2;
  get_dims(b, vox, d0, d1, d2, mn0, mn1, mn2);
  int G = d0 * d1 * d2;
  if (G > GMAX) G = GMAX;

  __shared__ int wsum[8];
  __shared__ int s_base;
  int t = threadIdx.x, lane = t & 31, warp = t >> 5;
  if (t == 0) s_base = 0;
  __syncthreads();

  for (int start = 0; start < G; start += blockDim.x) {
    int c = start + t;
    unsigned cnt = (c < G) ? g_cnt[b * GMAX + c] : 0u;
    int occ = cnt > 0u;
    unsigned m = __ballot_sync(0xffffffffu, occ);
    int wpre = __popc(m & ((1u << lane) - 1u));
    if (lane == 0) wsum[warp] = __popc(m);
    __syncthreads();
    int woff = 0;
    for (int w = 0; w < warp; ++w) woff += wsum[w];
    int tot = 0;
    for (int w = 0; w < 8; ++w) tot += wsum[w];
    if (occ) {
      int seg = s_base + woff + wpre;
      const double* s = &g_sums[((size_t)b * GMAX + c) * 3];
      double dc = (double)cnt;
      g_means[b * GMAX + seg] =
          make_float4((float)(s[0] / dc), (float)(s[1] / dc), (float)(s[2] / dc), 0.f);
    }
    __syncthreads();
    if (t == 0) s_base += tot;
    __syncthreads();
  }
  if (t == 0) g_numvox[b] = s_base;
}

// partitionable threefry sampling: bits[i] = o0^o1 of block(key_b, (0, i))
__global__ void k_sample(float* __restrict__ out, int L, KeyArr keys) {
  int b = blockIdx.y;
  int i = blockIdx.x * blockDim.x + threadIdx.x;
  if (i >= L) return;
  unsigned o0, o1;
  threefry2x32(keys.a[b], keys.b[b], 0u, (unsigned)i, o0, o1);
  unsigned bits = o0 ^ o1;
  float u = __uint_as_float((bits >> 9) | 0x3F800000u) - 1.0f;
  int nv = g_numvox[b];
  float prod = __fmul_rn(u, __int2float_rn(nv));
  int idx = (int)prod;                 // trunc toward zero, same as astype(int32)
  if (idx > nv - 1) idx = nv - 1;
  float4 mv = g_means[b * GMAX + idx];
  size_t ob = (size_t)b * 3 * L;
  out[ob + i]               = mv.x;
  out[ob + (size_t)L + i]   = mv.y;
  out[ob + (size_t)2 * L + i] = mv.z;
}

// ============================================================================
extern "C" void kernel_launch(void* const* d_in, const int* in_sizes, int n_in,
                              void* d_out, int out_size) {
  const float* x = (const float*)d_in[0];
  const int B = 16;
  const int N = in_sizes[0] / (B * 3);
  const int L1 = N / 2, L2 = N / 4;
  float* out1 = (float*)d_out;
  float* out2 = out1 + (size_t)B * 3 * L1;

  // JAX key derivation (partitionable/fold-like): key(42) -> split 2 -> split 16
  unsigned k1a, k1b, k2a, k2b;
  threefry2x32(0u, 42u, 0u, 0u, k1a, k1b);
  threefry2x32(0u, 42u, 0u, 1u, k2a, k2b);
  KeyArr K1, K2;
  for (int b = 0; b < B; ++b) {
    threefry2x32(k1a, k1b, 0u, (unsigned)b, K1.a[b], K1.b[b]);
    threefry2x32(k2a, k2b, 0u, (unsigned)b, K2.a[b], K2.b[b]);
  }

  dim3 th(256);
  int initBlocks = (B * GMAX + 255) / 256;

  // ---- layer 1: voxel 0.05, L1 samples
  k_init<<<initBlocks, th>>>(B);
  k_minmax<<<dim3(32, B * 3), th>>>(x, N);
  k_accum<<<dim3((N + 255) / 256, B), th>>>(x, N, 0.05f);
  k_compact<<<B, th>>>(0.05f);
  k_sample<<<dim3((L1 + 255) / 256, B), th>>>(out1, L1, K1);

  // ---- layer 2: voxel 0.10, L2 samples, input = layer-1 output
  k_init<<<initBlocks, th>>>(B);
  k_minmax<<<dim3(32, B * 3), th>>>(out1, L1);
  k_accum<<<dim3((L1 + 255) / 256, B), th>>>(out1, L1, 0.1f);
  k_compact<<<B, th>>>(0.1f);
  k_sample<<<dim3((L2 + 255) / 256, B), th>>>(out2, L2, K2);
}

// round 2
// speedup vs baseline: 2.7498x; 2.7498x over previous
#include <cuda_runtime.h>
#include <stdint.h>

// ============================================================================
// VoxelLayer: two cascaded voxel-grid downsamples (histogram + threefry-exact
// resample). R2: f32 v4 vector atomics, parallel block-scan compaction,
// fused layer-2 minmax into layer-1 sampling.
// ============================================================================

#define BMAX 16
#define GMAX 10648   // 22^3 upper bound on cells/batch (data is U[0,1))

// layer-separated buffers (single init at launch start)
__device__ float4   g_cells1[(size_t)BMAX * GMAX];  // {sx, sy, sz, count}
__device__ float4   g_cells2[(size_t)BMAX * GMAX];
__device__ float4   g_means1[(size_t)BMAX * GMAX];
__device__ float4   g_means2[(size_t)BMAX * GMAX];
__device__ int      g_numvox1[BMAX], g_numvox2[BMAX];
__device__ unsigned g_minEnc1[BMAX * 3], g_maxEnc1[BMAX * 3];
__device__ unsigned g_minEnc2[BMAX * 3], g_maxEnc2[BMAX * 3];

struct KeyArr { unsigned a[BMAX]; unsigned b[BMAX]; };

// ---- JAX threefry2x32 block
__host__ __device__ inline void threefry2x32(unsigned k0, unsigned k1,
                                             unsigned x0, unsigned x1,
                                             unsigned& o0, unsigned& o1) {
  unsigned ks2 = k0 ^ k1 ^ 0x1BD11BDAu;
  x0 += k0; x1 += k1;
#define TFR(r) { x0 += x1; x1 = (x1 << (r)) | (x1 >> (32 - (r))); x1 ^= x0; }
  TFR(13) TFR(15) TFR(26) TFR(6)
  x0 += k1;  x1 += ks2 + 1u;
  TFR(17) TFR(29) TFR(16) TFR(24)
  x0 += ks2; x1 += k0 + 2u;
  TFR(13) TFR(15) TFR(26) TFR(6)
  x0 += k0;  x1 += k1 + 3u;
  TFR(17) TFR(29) TFR(16) TFR(24)
  x0 += k1;  x1 += ks2 + 4u;
  TFR(13) TFR(15) TFR(26) TFR(6)
  x0 += ks2; x1 += k0 + 5u;
#undef TFR
  o0 = x0; o1 = x1;
}

// ---- order-preserving float<->uint encoding for atomicMin/Max
__device__ __forceinline__ unsigned fenc(float f) {
  unsigned u = __float_as_uint(f);
  return (u & 0x80000000u) ? ~u : (u | 0x80000000u);
}
__device__ __forceinline__ float fdec(unsigned e) {
  unsigned u = (e & 0x80000000u) ? (e & 0x7FFFFFFFu) : ~e;
  return __uint_as_float(u);
}

// ---- dims: identical fp path to JAX's max(floor((p-mn)/vox))+1 (monotone)
__device__ __forceinline__ void get_dims(const unsigned* minE, const unsigned* maxE,
                                         int b, float vox,
                                         int& d1, int& d2, int& G,
                                         float& mn0, float& mn1, float& mn2) {
  mn0 = fdec(minE[b * 3 + 0]);
  mn1 = fdec(minE[b * 3 + 1]);
  mn2 = fdec(minE[b * 3 + 2]);
  float mx0 = fdec(maxE[b * 3 + 0]);
  float mx1 = fdec(maxE[b * 3 + 1]);
  float mx2 = fdec(maxE[b * 3 + 2]);
  int d0 = (int)floorf(__fdiv_rn(__fsub_rn(mx0, mn0), vox)) + 1;
  d1 = (int)floorf(__fdiv_rn(__fsub_rn(mx1, mn1), vox)) + 1;
  d2 = (int)floorf(__fdiv_rn(__fsub_rn(mx2, mn2), vox)) + 1;
  G = d0 * d1 * d2;
  if (G > GMAX) G = GMAX;
}

// ============================================================================
__global__ void k_init() {
  int total = BMAX * GMAX;
  int stride = gridDim.x * blockDim.x;
  float4 z = make_float4(0.f, 0.f, 0.f, 0.f);
  for (int i = blockIdx.x * blockDim.x + threadIdx.x; i < total; i += stride) {
    g_cells1[i] = z;
    g_cells2[i] = z;
  }
  int t = blockIdx.x * blockDim.x + threadIdx.x;
  if (t < BMAX * 3) {
    g_minEnc1[t] = 0xFFFFFFFFu; g_maxEnc1[t] = 0u;
    g_minEnc2[t] = 0xFFFFFFFFu; g_maxEnc2[t] = 0u;
  }
}

__global__ void k_minmax(const float* __restrict__ x, int N,
                         unsigned* __restrict__ minE, unsigned* __restrict__ maxE) {
  int row = blockIdx.y;  // b*3 + d
  const float4* p = (const float4*)(x + (size_t)row * N);
  int N4 = N >> 2;
  unsigned mn = 0xFFFFFFFFu, mx = 0u;
  for (int i = blockIdx.x * blockDim.x + threadIdx.x; i < N4;
       i += gridDim.x * blockDim.x) {
    float4 v = p[i];
    unsigned e;
    e = fenc(v.x); mn = min(mn, e); mx = max(mx, e);
    e = fenc(v.y); mn = min(mn, e); mx = max(mx, e);
    e = fenc(v.z); mn = min(mn, e); mx = max(mx, e);
    e = fenc(v.w); mn = min(mn, e); mx = max(mx, e);
  }
#pragma unroll
  for (int o = 16; o; o >>= 1) {
    mn = min(mn, __shfl_down_sync(0xffffffffu, mn, o));
    mx = max(mx, __shfl_down_sync(0xffffffffu, mx, o));
  }
  __shared__ unsigned smn[32], smx[32];
  int lane = threadIdx.x & 31, warp = threadIdx.x >> 5;
  if (lane == 0) { smn[warp] = mn; smx[warp] = mx; }
  __syncthreads();
  if (warp == 0) {
    int nw = blockDim.x >> 5;
    mn = (lane < nw) ? smn[lane] : 0xFFFFFFFFu;
    mx = (lane < nw) ? smx[lane] : 0u;
#pragma unroll
    for (int o = 16; o; o >>= 1) {
      mn = min(mn, __shfl_down_sync(0xffffffffu, mn, o));
      mx = max(mx, __shfl_down_sync(0xffffffffu, mx, o));
    }
    if (lane == 0) { atomicMin(&minE[row], mn); atomicMax(&maxE[row], mx); }
  }
}

__global__ void k_accum(const float* __restrict__ x, int N, float vox,
                        float4* __restrict__ cells,
                        const unsigned* __restrict__ minE,
                        const unsigned* __restrict__ maxE) {
  int b = blockIdx.y;
  int i = blockIdx.x * blockDim.x + threadIdx.x;
  if (i >= N) return;
  int d1, d2, G; float mn0, mn1, mn2;
  get_dims(minE, maxE, b, vox, d1, d2, G, mn0, mn1, mn2);
  const float* base = x + (size_t)b * 3 * N;
  float p0 = base[i];
  float p1 = base[(size_t)N + i];
  float p2 = base[(size_t)2 * N + i];
  int v0 = (int)floorf(__fdiv_rn(__fsub_rn(p0, mn0), vox));
  int v1 = (int)floorf(__fdiv_rn(__fsub_rn(p1, mn1), vox));
  int v2 = (int)floorf(__fdiv_rn(__fsub_rn(p2, mn2), vox));
  int lin = (v0 * d1 + v1) * d2 + v2;
  if (lin < 0) lin = 0;
  if (lin > GMAX - 1) lin = GMAX - 1;  // safety only
  float4* c = &cells[(size_t)b * GMAX + lin];
  asm volatile("red.global.add.v4.f32 [%0], {%1, %2, %3, %4};"
               :: "l"(c), "f"(p0), "f"(p1), "f"(p2), "f"(1.0f) : "memory");
}

// one block (1024 thr) per batch: block-scan compaction, lin order preserved
__global__ void k_compact(const float4* __restrict__ cells,
                          float4* __restrict__ means, int* __restrict__ numvox,
                          const unsigned* __restrict__ minE,
                          const unsigned* __restrict__ maxE, float vox) {
  int b = blockIdx.x;
  int d1, d2, G; float mn0, mn1, mn2;
  get_dims(minE, maxE, b, vox, d1, d2, G, mn0, mn1, mn2);

  int t = threadIdx.x, lane = t & 31, w = t >> 5;
  int ck = (G + 1023) >> 10;                 // cells per thread (<= 11)
  int start = t * ck;
  int end = min(start + ck, G);
  const float4* cb = cells + (size_t)b * GMAX;

  int cnt = 0;
  for (int c = start; c < end; ++c)
    if (cb[c].w > 0.f) cnt++;

  // block exclusive scan over per-thread counts
  __shared__ int warpTot[32];
  __shared__ int s_tot;
  int p = cnt;
#pragma unroll
  for (int o = 1; o < 32; o <<= 1) {
    int n = __shfl_up_sync(0xffffffffu, p, o);
    if (lane >= o) p += n;
  }
  if (lane == 31) warpTot[w] = p;
  __syncthreads();
  if (w == 0) {
    int s = warpTot[lane];
    int q = s;
#pragma unroll
    for (int o = 1; o < 32; o <<= 1) {
      int n = __shfl_up_sync(0xffffffffu, q, o);
      if (lane >= o) q += n;
    }
    warpTot[lane] = q - s;          // exclusive warp offsets
    if (lane == 31) s_tot = q;      // grand total
  }
  __syncthreads();

  int off = (p - cnt) + warpTot[w];
  float4* mb = means + (size_t)b * GMAX;
  for (int c = start; c < end; ++c) {
    float4 s = cb[c];
    if (s.w > 0.f) {
      mb[off++] = make_float4(__fdiv_rn(s.x, s.w), __fdiv_rn(s.y, s.w),
                              __fdiv_rn(s.z, s.w), 0.f);
    }
  }
  if (t == 0) numvox[b] = s_tot;
}

// partitionable threefry sampling; optionally track min/max for next layer
template <bool TRACK>
__global__ void k_sample(float* __restrict__ out, int L, KeyArr keys,
                         const float4* __restrict__ means,
                         const int* __restrict__ numvox,
                         unsigned* __restrict__ minE2,
                         unsigned* __restrict__ maxE2) {
  int b = blockIdx.y;
  int i = blockIdx.x * blockDim.x + threadIdx.x;
  float4 mv = make_float4(0.f, 0.f, 0.f, 0.f);
  bool act = i < L;
  if (act) {
    unsigned o0, o1;
    threefry2x32(keys.a[b], keys.b[b], 0u, (unsigned)i, o0, o1);
    unsigned bits = o0 ^ o1;
    float u = __uint_as_float((bits >> 9) | 0x3F800000u) - 1.0f;
    int nv = numvox[b];
    float prod = __fmul_rn(u, __int2float_rn(nv));
    int idx = (int)prod;               // trunc == astype(int32)
    if (idx > nv - 1) idx = nv - 1;
    mv = means[(size_t)b * GMAX + idx];
    size_t ob = (size_t)b * 3 * L;
    out[ob + i]                 = mv.x;
    out[ob + (size_t)L + i]     = mv.y;
    out[ob + (size_t)2 * L + i] = mv.z;
  }
  if (TRACK) {
    unsigned mn0 = act ? fenc(mv.x) : 0xFFFFFFFFu, mx0 = act ? fenc(mv.x) : 0u;
    unsigned mn1 = act ? fenc(mv.y) : 0xFFFFFFFFu, mx1 = act ? fenc(mv.y) : 0u;
    unsigned mn2 = act ? fenc(mv.z) : 0xFFFFFFFFu, mx2 = act ? fenc(mv.z) : 0u;
#pragma unroll
    for (int o = 16; o; o >>= 1) {
      mn0 = min(mn0, __shfl_down_sync(0xffffffffu, mn0, o));
      mx0 = max(mx0, __shfl_down_sync(0xffffffffu, mx0, o));
      mn1 = min(mn1, __shfl_down_sync(0xffffffffu, mn1, o));
      mx1 = max(mx1, __shfl_down_sync(0xffffffffu, mx1, o));
      mn2 = min(mn2, __shfl_down_sync(0xffffffffu, mn2, o));
      mx2 = max(mx2, __shfl_down_sync(0xffffffffu, mx2, o));
    }
    __shared__ unsigned sm[6][8];
    int lane = threadIdx.x & 31, w = threadIdx.x >> 5;
    if (lane == 0) {
      sm[0][w] = mn0; sm[1][w] = mx0; sm[2][w] = mn1;
      sm[3][w] = mx1; sm[4][w] = mn2; sm[5][w] = mx2;
    }
    __syncthreads();
    if (w == 0 && lane < 8) {
      // serial-8 reduce by lane 0 of warp 0 is fine; do tree in lane dim
    }
    if (threadIdx.x == 0) {
      unsigned a0 = 0xFFFFFFFFu, a1 = 0u, a2 = 0xFFFFFFFFu,
               a3 = 0u, a4 = 0xFFFFFFFFu, a5 = 0u;
      int nw = blockDim.x >> 5;
      for (int k = 0; k < nw; ++k) {
        a0 = min(a0, sm[0][k]); a1 = max(a1, sm[1][k]);
        a2 = min(a2, sm[2][k]); a3 = max(a3, sm[3][k]);
        a4 = min(a4, sm[4][k]); a5 = max(a5, sm[5][k]);
      }
      atomicMin(&minE2[b * 3 + 0], a0); atomicMax(&maxE2[b * 3 + 0], a1);
      atomicMin(&minE2[b * 3 + 1], a2); atomicMax(&maxE2[b * 3 + 1], a3);
      atomicMin(&minE2[b * 3 + 2], a4); atomicMax(&maxE2[b * 3 + 2], a5);
    }
  }
}

// ============================================================================
extern "C" void kernel_launch(void* const* d_in, const int* in_sizes, int n_in,
                              void* d_out, int out_size) {
  const float* x = (const float*)d_in[0];
  const int B = 16;
  const int N = in_sizes[0] / (B * 3);
  const int L1 = N / 2, L2 = N / 4;
  float* out1 = (float*)d_out;
  float* out2 = out1 + (size_t)B * 3 * L1;

  // JAX key derivation (partitionable): key(42) -> split 2 -> split 16
  unsigned k1a, k1b, k2a, k2b;
  threefry2x32(0u, 42u, 0u, 0u, k1a, k1b);
  threefry2x32(0u, 42u, 0u, 1u, k2a, k2b);
  KeyArr K1, K2;
  for (int b = 0; b < B; ++b) {
    threefry2x32(k1a, k1b, 0u, (unsigned)b, K1.a[b], K1.b[b]);
    threefry2x32(k2a, k2b, 0u, (unsigned)b, K2.a[b], K2.b[b]);
  }

  // device-symbol addresses (host-side lookups are graph-safe: done here, but
  // cudaGetSymbolAddress is not capture-hostile; use static cached pointers)
  static float4 *cells1 = nullptr, *cells2 = nullptr, *means1 = nullptr, *means2 = nullptr;
  static int *numvox1 = nullptr, *numvox2 = nullptr;
  static unsigned *minE1 = nullptr, *maxE1 = nullptr, *minE2 = nullptr, *maxE2 = nullptr;
  if (!cells1) {
    cudaGetSymbolAddress((void**)&cells1, g_cells1);
    cudaGetSymbolAddress((void**)&cells2, g_cells2);
    cudaGetSymbolAddress((void**)&means1, g_means1);
    cudaGetSymbolAddress((void**)&means2, g_means2);
    cudaGetSymbolAddress((void**)&numvox1, g_numvox1);
    cudaGetSymbolAddress((void**)&numvox2, g_numvox2);
    cudaGetSymbolAddress((void**)&minE1, g_minEnc1);
    cudaGetSymbolAddress((void**)&maxE1, g_maxEnc1);
    cudaGetSymbolAddress((void**)&minE2, g_minEnc2);
    cudaGetSymbolAddress((void**)&maxE2, g_maxEnc2);
  }

  dim3 th(256);

  k_init<<<256, th>>>();

  // ---- layer 1: voxel 0.05
  k_minmax<<<dim3(16, B * 3), th>>>(x, N, minE1, maxE1);
  k_accum<<<dim3((N + 255) / 256, B), th>>>(x, N, 0.05f, cells1, minE1, maxE1);
  k_compact<<<B, 1024>>>(cells1, means1, numvox1, minE1, maxE1, 0.05f);
  k_sample<true><<<dim3((L1 + 255) / 256, B), th>>>(out1, L1, K1, means1, numvox1,
                                                    minE2, maxE2);

  // ---- layer 2: voxel 0.10 (min/max already tracked by layer-1 sample)
  k_accum<<<dim3((L1 + 255) / 256, B), th>>>(out1, L1, 0.1f, cells2, minE2, maxE2);
  k_compact<<<B, 1024>>>(cells2, means2, numvox2, minE2, maxE2, 0.1f);
  k_sample<false><<<dim3((L2 + 255) / 256, B), th>>>(out2, L2, K2, means2, numvox2,
                                                     nullptr, nullptr);
}

// round 3
// speedup vs baseline: 3.2465x; 1.1806x over previous
#include <cuda_runtime.h>
#include <stdint.h>

// ============================================================================
// VoxelLayer: two cascaded voxel-grid downsamples (dense histogram + threefry-
// exact resample). R3: two-phase parallel compaction (128 blocks), float4
// point loads in accum, capped layer-2 grid.
// ============================================================================

#define BMAX 16
#define GMAX 10648   // 22^3 upper bound on cells/batch for layer 1 (U[0,1) data)
#define GMAX2 2048   // layer-2: dims <= 11 -> 1331 cells max
#define CH 8         // compaction chunks per batch

__device__ float4   g_cells1[(size_t)BMAX * GMAX];  // {sx, sy, sz, count}
__device__ float4   g_cells2[(size_t)BMAX * GMAX2];
__device__ float4   g_means1[(size_t)BMAX * GMAX];
__device__ float4   g_means2[(size_t)BMAX * GMAX2];
__device__ int      g_numvox1[BMAX], g_numvox2[BMAX];
__device__ int      g_chunk1[BMAX * CH], g_chunk2[BMAX * CH];
__device__ unsigned g_minEnc1[BMAX * 3], g_maxEnc1[BMAX * 3];
__device__ unsigned g_minEnc2[BMAX * 3], g_maxEnc2[BMAX * 3];

struct KeyArr { unsigned a[BMAX]; unsigned b[BMAX]; };

// ---- JAX threefry2x32 block
__host__ __device__ inline void threefry2x32(unsigned k0, unsigned k1,
                                             unsigned x0, unsigned x1,
                                             unsigned& o0, unsigned& o1) {
  unsigned ks2 = k0 ^ k1 ^ 0x1BD11BDAu;
  x0 += k0; x1 += k1;
#define TFR(r) { x0 += x1; x1 = (x1 << (r)) | (x1 >> (32 - (r))); x1 ^= x0; }
  TFR(13) TFR(15) TFR(26) TFR(6)
  x0 += k1;  x1 += ks2 + 1u;
  TFR(17) TFR(29) TFR(16) TFR(24)
  x0 += ks2; x1 += k0 + 2u;
  TFR(13) TFR(15) TFR(26) TFR(6)
  x0 += k0;  x1 += k1 + 3u;
  TFR(17) TFR(29) TFR(16) TFR(24)
  x0 += k1;  x1 += ks2 + 4u;
  TFR(13) TFR(15) TFR(26) TFR(6)
  x0 += ks2; x1 += k0 + 5u;
#undef TFR
  o0 = x0; o1 = x1;
}

// ---- order-preserving float<->uint encoding for atomicMin/Max
__device__ __forceinline__ unsigned fenc(float f) {
  unsigned u = __float_as_uint(f);
  return (u & 0x80000000u) ? ~u : (u | 0x80000000u);
}
__device__ __forceinline__ float fdec(unsigned e) {
  unsigned u = (e & 0x80000000u) ? (e & 0x7FFFFFFFu) : ~e;
  return __uint_as_float(u);
}

// ---- dims: identical fp path to JAX's max(floor((p-mn)/vox))+1 (monotone)
__device__ __forceinline__ void get_dims(const unsigned* minE, const unsigned* maxE,
                                         int b, float vox, int cap,
                                         int& d1, int& d2, int& G,
                                         float& mn0, float& mn1, float& mn2) {
  mn0 = fdec(minE[b * 3 + 0]);
  mn1 = fdec(minE[b * 3 + 1]);
  mn2 = fdec(minE[b * 3 + 2]);
  float mx0 = fdec(maxE[b * 3 + 0]);
  float mx1 = fdec(maxE[b * 3 + 1]);
  float mx2 = fdec(maxE[b * 3 + 2]);
  int d0 = (int)floorf(__fdiv_rn(__fsub_rn(mx0, mn0), vox)) + 1;
  d1 = (int)floorf(__fdiv_rn(__fsub_rn(mx1, mn1), vox)) + 1;
  d2 = (int)floorf(__fdiv_rn(__fsub_rn(mx2, mn2), vox)) + 1;
  G = d0 * d1 * d2;
  if (G > cap) G = cap;
}

// ============================================================================
__global__ void k_init() {
  int stride = gridDim.x * blockDim.x;
  int tid = blockIdx.x * blockDim.x + threadIdx.x;
  float4 z = make_float4(0.f, 0.f, 0.f, 0.f);
  for (int i = tid; i < BMAX * GMAX; i += stride) g_cells1[i] = z;
  for (int i = tid; i < BMAX * GMAX2; i += stride) g_cells2[i] = z;
  if (tid < BMAX * 3) {
    g_minEnc1[tid] = 0xFFFFFFFFu; g_maxEnc1[tid] = 0u;
    g_minEnc2[tid] = 0xFFFFFFFFu; g_maxEnc2[tid] = 0u;
  }
}

__global__ void k_minmax(const float* __restrict__ x, int N,
                         unsigned* __restrict__ minE, unsigned* __restrict__ maxE) {
  int row = blockIdx.y;  // b*3 + d
  const float4* p = (const float4*)(x + (size_t)row * N);
  int N4 = N >> 2;
  unsigned mn = 0xFFFFFFFFu, mx = 0u;
  for (int i = blockIdx.x * blockDim.x + threadIdx.x; i < N4;
       i += gridDim.x * blockDim.x) {
    float4 v = p[i];
    unsigned e;
    e = fenc(v.x); mn = min(mn, e); mx = max(mx, e);
    e = fenc(v.y); mn = min(mn, e); mx = max(mx, e);
    e = fenc(v.z); mn = min(mn, e); mx = max(mx, e);
    e = fenc(v.w); mn = min(mn, e); mx = max(mx, e);
  }
#pragma unroll
  for (int o = 16; o; o >>= 1) {
    mn = min(mn, __shfl_down_sync(0xffffffffu, mn, o));
    mx = max(mx, __shfl_down_sync(0xffffffffu, mx, o));
  }
  __shared__ unsigned smn[32], smx[32];
  int lane = threadIdx.x & 31, warp = threadIdx.x >> 5;
  if (lane == 0) { smn[warp] = mn; smx[warp] = mx; }
  __syncthreads();
  if (warp == 0) {
    int nw = blockDim.x >> 5;
    mn = (lane < nw) ? smn[lane] : 0xFFFFFFFFu;
    mx = (lane < nw) ? smx[lane] : 0u;
#pragma unroll
    for (int o = 16; o; o >>= 1) {
      mn = min(mn, __shfl_down_sync(0xffffffffu, mn, o));
      mx = max(mx, __shfl_down_sync(0xffffffffu, mx, o));
    }
    if (lane == 0) { atomicMin(&minE[row], mn); atomicMax(&maxE[row], mx); }
  }
}

// 4 points per thread via float4 row loads
__global__ void k_accum(const float* __restrict__ x, int N, float vox,
                        float4* __restrict__ cells, int cellStride, int cap,
                        const unsigned* __restrict__ minE,
                        const unsigned* __restrict__ maxE) {
  int b = blockIdx.y;
  int i4 = blockIdx.x * blockDim.x + threadIdx.x;
  int N4 = N >> 2;
  if (i4 >= N4) return;
  int d1, d2, G; float mn0, mn1, mn2;
  get_dims(minE, maxE, b, vox, cap, d1, d2, G, mn0, mn1, mn2);
  const float* base = x + (size_t)b * 3 * N;
  float4 r0 = ((const float4*)base)[i4];
  float4 r1 = ((const float4*)(base + N))[i4];
  float4 r2 = ((const float4*)(base + 2 * (size_t)N))[i4];
  float4* cb = cells + (size_t)b * cellStride;
  const float px[4] = {r0.x, r0.y, r0.z, r0.w};
  const float py[4] = {r1.x, r1.y, r1.z, r1.w};
  const float pz[4] = {r2.x, r2.y, r2.z, r2.w};
#pragma unroll
  for (int k = 0; k < 4; ++k) {
    int v0 = (int)floorf(__fdiv_rn(__fsub_rn(px[k], mn0), vox));
    int v1 = (int)floorf(__fdiv_rn(__fsub_rn(py[k], mn1), vox));
    int v2 = (int)floorf(__fdiv_rn(__fsub_rn(pz[k], mn2), vox));
    int lin = (v0 * d1 + v1) * d2 + v2;
    if (lin < 0) lin = 0;
    if (lin > cap - 1) lin = cap - 1;  // safety only
    float4* c = &cb[lin];
    asm volatile("red.global.add.v4.f32 [%0], {%1, %2, %3, %4};"
                 :: "l"(c), "f"(px[k]), "f"(py[k]), "f"(pz[k]), "f"(1.0f)
                 : "memory");
  }
}

// ---- phase 1: per-chunk occupied-cell counts. grid (CH, B), 256 threads
__global__ void k_count(const float4* __restrict__ cells, int cellStride, int cap,
                        const unsigned* __restrict__ minE,
                        const unsigned* __restrict__ maxE, float vox,
                        int* __restrict__ chunkCnt) {
  int b = blockIdx.y, chunk = blockIdx.x;
  int d1, d2, G; float mn0, mn1, mn2;
  get_dims(minE, maxE, b, vox, cap, d1, d2, G, mn0, mn1, mn2);
  int per = (G + CH - 1) / CH;
  int c0 = chunk * per, c1 = min(c0 + per, G);
  const float4* cb = cells + (size_t)b * cellStride;
  int cnt = 0;
  for (int c = c0 + threadIdx.x; c < c1; c += blockDim.x)
    cnt += (cb[c].w > 0.f);
#pragma unroll
  for (int o = 16; o; o >>= 1) cnt += __shfl_down_sync(0xffffffffu, cnt, o);
  __shared__ int sw[8];
  int lane = threadIdx.x & 31, w = threadIdx.x >> 5;
  if (lane == 0) sw[w] = cnt;
  __syncthreads();
  if (threadIdx.x == 0) {
    int tot = 0;
#pragma unroll
    for (int k = 0; k < 8; ++k) tot += sw[k];
    chunkCnt[b * CH + chunk] = tot;
  }
}

// ---- phase 2: ordered compaction per chunk. grid (CH, B), 256 threads
__global__ void k_write(const float4* __restrict__ cells, int cellStride, int cap,
                        const unsigned* __restrict__ minE,
                        const unsigned* __restrict__ maxE, float vox,
                        const int* __restrict__ chunkCnt,
                        float4* __restrict__ means, int* __restrict__ numvox) {
  int b = blockIdx.y, chunk = blockIdx.x;
  int d1, d2, G; float mn0, mn1, mn2;
  get_dims(minE, maxE, b, vox, cap, d1, d2, G, mn0, mn1, mn2);
  int per = (G + CH - 1) / CH;
  int c0 = chunk * per, c1 = min(c0 + per, G);

  int base = 0;
  for (int k = 0; k < chunk; ++k) base += chunkCnt[b * CH + k];

  int t = threadIdx.x, lane = t & 31, w = t >> 5;
  int n = max(c1 - c0, 0);
  int ck = (n + (int)blockDim.x - 1) / (int)blockDim.x;  // contiguous cells/thread
  int start = c0 + t * ck;
  int end = min(start + ck, c1);
  const float4* cb = cells + (size_t)b * cellStride;

  int cnt = 0;
  for (int c = start; c < end; ++c)
    if (cb[c].w > 0.f) cnt++;

  // block exclusive scan over per-thread counts (8 warps)
  __shared__ int warpTot[8];
  int p = cnt;
#pragma unroll
  for (int o = 1; o < 32; o <<= 1) {
    int v = __shfl_up_sync(0xffffffffu, p, o);
    if (lane >= o) p += v;
  }
  if (lane == 31) warpTot[w] = p;
  __syncthreads();
  int woff = 0;
  for (int k = 0; k < w; ++k) woff += warpTot[k];

  int off = base + woff + (p - cnt);
  float4* mb = means + (size_t)b * cellStride;
  for (int c = start; c < end; ++c) {
    float4 s = cb[c];
    if (s.w > 0.f) {
      mb[off++] = make_float4(__fdiv_rn(s.x, s.w), __fdiv_rn(s.y, s.w),
                              __fdiv_rn(s.z, s.w), 0.f);
    }
  }
  if (chunk == CH - 1 && t == 0) {
    int tot = 0;
    for (int k = 0; k < CH; ++k) tot += chunkCnt[b * CH + k];
    numvox[b] = tot;
  }
}

// partitionable threefry sampling; optionally track min/max for next layer
template <bool TRACK>
__global__ void k_sample(float* __restrict__ out, int L, KeyArr keys,
                         const float4* __restrict__ means, int cellStride,
                         const int* __restrict__ numvox,
                         unsigned* __restrict__ minE2,
                         unsigned* __restrict__ maxE2) {
  int b = blockIdx.y;
  int i = blockIdx.x * blockDim.x + threadIdx.x;
  float4 mv = make_float4(0.f, 0.f, 0.f, 0.f);
  bool act = i < L;
  if (act) {
    unsigned o0, o1;
    threefry2x32(keys.a[b], keys.b[b], 0u, (unsigned)i, o0, o1);
    unsigned bits = o0 ^ o1;
    float u = __uint_as_float((bits >> 9) | 0x3F800000u) - 1.0f;
    int nv = numvox[b];
    float prod = __fmul_rn(u, __int2float_rn(nv));
    int idx = (int)prod;               // trunc == astype(int32)
    if (idx > nv - 1) idx = nv - 1;
    mv = means[(size_t)b * cellStride + idx];
    size_t ob = (size_t)b * 3 * L;
    out[ob + i]                 = mv.x;
    out[ob + (size_t)L + i]     = mv.y;
    out[ob + (size_t)2 * L + i] = mv.z;
  }
  if (TRACK) {
    unsigned mn0 = act ? fenc(mv.x) : 0xFFFFFFFFu, mx0 = act ? fenc(mv.x) : 0u;
    unsigned mn1 = act ? fenc(mv.y) : 0xFFFFFFFFu, mx1 = act ? fenc(mv.y) : 0u;
    unsigned mn2 = act ? fenc(mv.z) : 0xFFFFFFFFu, mx2 = act ? fenc(mv.z) : 0u;
#pragma unroll
    for (int o = 16; o; o >>= 1) {
      mn0 = min(mn0, __shfl_down_sync(0xffffffffu, mn0, o));
      mx0 = max(mx0, __shfl_down_sync(0xffffffffu, mx0, o));
      mn1 = min(mn1, __shfl_down_sync(0xffffffffu, mn1, o));
      mx1 = max(mx1, __shfl_down_sync(0xffffffffu, mx1, o));
      mn2 = min(mn2, __shfl_down_sync(0xffffffffu, mn2, o));
      mx2 = max(mx2, __shfl_down_sync(0xffffffffu, mx2, o));
    }
    __shared__ unsigned sm[6][8];
    int lane = threadIdx.x & 31, w = threadIdx.x >> 5;
    if (lane == 0) {
      sm[0][w] = mn0; sm[1][w] = mx0; sm[2][w] = mn1;
      sm[3][w] = mx1; sm[4][w] = mn2; sm[5][w] = mx2;
    }
    __syncthreads();
    if (threadIdx.x == 0) {
      unsigned a0 = 0xFFFFFFFFu, a1 = 0u, a2 = 0xFFFFFFFFu,
               a3 = 0u, a4 = 0xFFFFFFFFu, a5 = 0u;
      int nw = blockDim.x >> 5;
      for (int k = 0; k < nw; ++k) {
        a0 = min(a0, sm[0][k]); a1 = max(a1, sm[1][k]);
        a2 = min(a2, sm[2][k]); a3 = max(a3, sm[3][k]);
        a4 = min(a4, sm[4][k]); a5 = max(a5, sm[5][k]);
      }
      atomicMin(&minE2[b * 3 + 0], a0); atomicMax(&maxE2[b * 3 + 0], a1);
      atomicMin(&minE2[b * 3 + 1], a2); atomicMax(&maxE2[b * 3 + 1], a3);
      atomicMin(&minE2[b * 3 + 2], a4); atomicMax(&maxE2[b * 3 + 2], a5);
    }
  }
}

// ============================================================================
extern "C" void kernel_launch(void* const* d_in, const int* in_sizes, int n_in,
                              void* d_out, int out_size) {
  const float* x = (const float*)d_in[0];
  const int B = 16;
  const int N = in_sizes[0] / (B * 3);
  const int L1 = N / 2, L2 = N / 4;
  float* out1 = (float*)d_out;
  float* out2 = out1 + (size_t)B * 3 * L1;

  // JAX key derivation (partitionable): key(42) -> split 2 -> split 16
  unsigned k1a, k1b, k2a, k2b;
  threefry2x32(0u, 42u, 0u, 0u, k1a, k1b);
  threefry2x32(0u, 42u, 0u, 1u, k2a, k2b);
  KeyArr K1, K2;
  for (int b = 0; b < B; ++b) {
    threefry2x32(k1a, k1b, 0u, (unsigned)b, K1.a[b], K1.b[b]);
    threefry2x32(k2a, k2b, 0u, (unsigned)b, K2.a[b], K2.b[b]);
  }

  static float4 *cells1 = nullptr, *cells2, *means1, *means2;
  static int *numvox1, *numvox2, *chunk1, *chunk2;
  static unsigned *minE1, *maxE1, *minE2, *maxE2;
  if (!cells1) {
    cudaGetSymbolAddress((void**)&cells1, g_cells1);
    cudaGetSymbolAddress((void**)&cells2, g_cells2);
    cudaGetSymbolAddress((void**)&means1, g_means1);
    cudaGetSymbolAddress((void**)&means2, g_means2);
    cudaGetSymbolAddress((void**)&numvox1, g_numvox1);
    cudaGetSymbolAddress((void**)&numvox2, g_numvox2);
    cudaGetSymbolAddress((void**)&chunk1, g_chunk1);
    cudaGetSymbolAddress((void**)&chunk2, g_chunk2);
    cudaGetSymbolAddress((void**)&minE1, g_minEnc1);
    cudaGetSymbolAddress((void**)&maxE1, g_maxEnc1);
    cudaGetSymbolAddress((void**)&minE2, g_minEnc2);
    cudaGetSymbolAddress((void**)&maxE2, g_maxEnc2);
  }

  dim3 th(256);

  k_init<<<148, th>>>();

  // ---- layer 1: voxel 0.05
  k_minmax<<<dim3(16, B * 3), th>>>(x, N, minE1, maxE1);
  k_accum<<<dim3((N / 4 + 255) / 256, B), th>>>(x, N, 0.05f, cells1, GMAX, GMAX,
                                                minE1, maxE1);
  k_count<<<dim3(CH, B), th>>>(cells1, GMAX, GMAX, minE1, maxE1, 0.05f, chunk1);
  k_write<<<dim3(CH, B), th>>>(cells1, GMAX, GMAX, minE1, maxE1, 0.05f, chunk1,
                               means1, numvox1);
  k_sample<true><<<dim3((L1 + 255) / 256, B), th>>>(out1, L1, K1, means1, GMAX,
                                                    numvox1, minE2, maxE2);

  // ---- layer 2: voxel 0.10 (min/max tracked by layer-1 sample)
  k_accum<<<dim3((L1 / 4 + 255) / 256, B), th>>>(out1, L1, 0.1f, cells2, GMAX2,
                                                 GMAX2, minE2, maxE2);
  k_count<<<dim3(CH, B), th>>>(cells2, GMAX2, GMAX2, minE2, maxE2, 0.1f, chunk2);
  k_write<<<dim3(CH, B), th>>>(cells2, GMAX2, GMAX2, minE2, maxE2, 0.1f, chunk2,
                               means2, numvox2);
  k_sample<false><<<dim3((L2 + 255) / 256, B), th>>>(out2, L2, K2, means2, GMAX2,
                                                     numvox2, nullptr, nullptr);
}

// round 4
// speedup vs baseline: 3.9597x; 1.2197x over previous
#include <cuda_runtime.h>
#include <stdint.h>

// ============================================================================
// VoxelLayer: two cascaded voxel-grid downsamples (dense histogram + threefry-
// exact resample). R4: cluster-fused compaction (count+scan+write in one
// kernel via DSMEM), vectorized sampling (4 samples/thread).
// ============================================================================

#define BMAX 16
#define GMAX 10648   // 22^3 upper bound on cells/batch for layer 1 (U[0,1))
#define GMAX2 2048   // layer-2: dims <= 11 -> 1331 cells max
#define CH 8         // compaction chunks per batch == cluster size
#define PERMAX 1344  // ceil(GMAX/CH) rounded up

__device__ float4   g_cells1[(size_t)BMAX * GMAX];  // {sx, sy, sz, count}
__device__ float4   g_cells2[(size_t)BMAX * GMAX2];
__device__ float4   g_means1[(size_t)BMAX * GMAX];
__device__ float4   g_means2[(size_t)BMAX * GMAX2];
__device__ int      g_numvox1[BMAX], g_numvox2[BMAX];
__device__ unsigned g_minEnc1[BMAX * 3], g_maxEnc1[BMAX * 3];
__device__ unsigned g_minEnc2[BMAX * 3], g_maxEnc2[BMAX * 3];

struct KeyArr { unsigned a[BMAX]; unsigned b[BMAX]; };

// ---- JAX threefry2x32 block
__host__ __device__ inline void threefry2x32(unsigned k0, unsigned k1,
                                             unsigned x0, unsigned x1,
                                             unsigned& o0, unsigned& o1) {
  unsigned ks2 = k0 ^ k1 ^ 0x1BD11BDAu;
  x0 += k0; x1 += k1;
#define TFR(r) { x0 += x1; x1 = (x1 << (r)) | (x1 >> (32 - (r))); x1 ^= x0; }
  TFR(13) TFR(15) TFR(26) TFR(6)
  x0 += k1;  x1 += ks2 + 1u;
  TFR(17) TFR(29) TFR(16) TFR(24)
  x0 += ks2; x1 += k0 + 2u;
  TFR(13) TFR(15) TFR(26) TFR(6)
  x0 += k0;  x1 += k1 + 3u;
  TFR(17) TFR(29) TFR(16) TFR(24)
  x0 += k1;  x1 += ks2 + 4u;
  TFR(13) TFR(15) TFR(26) TFR(6)
  x0 += ks2; x1 += k0 + 5u;
#undef TFR
  o0 = x0; o1 = x1;
}

// ---- order-preserving float<->uint encoding for atomicMin/Max
__device__ __forceinline__ unsigned fenc(float f) {
  unsigned u = __float_as_uint(f);
  return (u & 0x80000000u) ? ~u : (u | 0x80000000u);
}
__device__ __forceinline__ float fdec(unsigned e) {
  unsigned u = (e & 0x80000000u) ? (e & 0x7FFFFFFFu) : ~e;
  return __uint_as_float(u);
}

__device__ __forceinline__ uint32_t smem_u32(const void* p) {
  uint32_t a;
  asm("{ .reg .u64 t; cvta.to.shared.u64 t, %1; cvt.u32.u64 %0, t; }"
      : "=r"(a) : "l"(p));
  return a;
}
__device__ __forceinline__ int dsmem_ld(uint32_t laddr, uint32_t rank) {
  uint32_t ra;
  asm("mapa.shared::cluster.u32 %0, %1, %2;" : "=r"(ra) : "r"(laddr), "r"(rank));
  int v;
  asm volatile("ld.shared::cluster.s32 %0, [%1];" : "=r"(v) : "r"(ra));
  return v;
}

// ---- dims: identical fp path to JAX's max(floor((p-mn)/vox))+1 (monotone)
__device__ __forceinline__ void get_dims(const unsigned* minE, const unsigned* maxE,
                                         int b, float vox, int cap,
                                         int& d1, int& d2, int& G,
                                         float& mn0, float& mn1, float& mn2) {
  mn0 = fdec(minE[b * 3 + 0]);
  mn1 = fdec(minE[b * 3 + 1]);
  mn2 = fdec(minE[b * 3 + 2]);
  float mx0 = fdec(maxE[b * 3 + 0]);
  float mx1 = fdec(maxE[b * 3 + 1]);
  float mx2 = fdec(maxE[b * 3 + 2]);
  int d0 = (int)floorf(__fdiv_rn(__fsub_rn(mx0, mn0), vox)) + 1;
  d1 = (int)floorf(__fdiv_rn(__fsub_rn(mx1, mn1), vox)) + 1;
  d2 = (int)floorf(__fdiv_rn(__fsub_rn(mx2, mn2), vox)) + 1;
  G = d0 * d1 * d2;
  if (G > cap) G = cap;
}

// ============================================================================
__global__ void k_init() {
  int stride = gridDim.x * blockDim.x;
  int tid = blockIdx.x * blockDim.x + threadIdx.x;
  float4 z = make_float4(0.f, 0.f, 0.f, 0.f);
  for (int i = tid; i < BMAX * GMAX; i += stride) g_cells1[i] = z;
  for (int i = tid; i < BMAX * GMAX2; i += stride) g_cells2[i] = z;
  if (tid < BMAX * 3) {
    g_minEnc1[tid] = 0xFFFFFFFFu; g_maxEnc1[tid] = 0u;
    g_minEnc2[tid] = 0xFFFFFFFFu; g_maxEnc2[tid] = 0u;
  }
}

__global__ void k_minmax(const float* __restrict__ x, int N,
                         unsigned* __restrict__ minE, unsigned* __restrict__ maxE) {
  int row = blockIdx.y;  // b*3 + d
  const float4* p = (const float4*)(x + (size_t)row * N);
  int N4 = N >> 2;
  unsigned mn = 0xFFFFFFFFu, mx = 0u;
  for (int i = blockIdx.x * blockDim.x + threadIdx.x; i < N4;
       i += gridDim.x * blockDim.x) {
    float4 v = p[i];
    unsigned e;
    e = fenc(v.x); mn = min(mn, e); mx = max(mx, e);
    e = fenc(v.y); mn = min(mn, e); mx = max(mx, e);
    e = fenc(v.z); mn = min(mn, e); mx = max(mx, e);
    e = fenc(v.w); mn = min(mn, e); mx = max(mx, e);
  }
#pragma unroll
  for (int o = 16; o; o >>= 1) {
    mn = min(mn, __shfl_down_sync(0xffffffffu, mn, o));
    mx = max(mx, __shfl_down_sync(0xffffffffu, mx, o));
  }
  __shared__ unsigned smn[32], smx[32];
  int lane = threadIdx.x & 31, warp = threadIdx.x >> 5;
  if (lane == 0) { smn[warp] = mn; smx[warp] = mx; }
  __syncthreads();
  if (warp == 0) {
    int nw = blockDim.x >> 5;
    mn = (lane < nw) ? smn[lane] : 0xFFFFFFFFu;
    mx = (lane < nw) ? smx[lane] : 0u;
#pragma unroll
    for (int o = 16; o; o >>= 1) {
      mn = min(mn, __shfl_down_sync(0xffffffffu, mn, o));
      mx = max(mx, __shfl_down_sync(0xffffffffu, mx, o));
    }
    if (lane == 0) { atomicMin(&minE[row], mn); atomicMax(&maxE[row], mx); }
  }
}

// 4 points per thread via float4 row loads; one red.v4.f32 per point
__global__ void k_accum(const float* __restrict__ x, int N, float vox,
                        float4* __restrict__ cells, int cellStride, int cap,
                        const unsigned* __restrict__ minE,
                        const unsigned* __restrict__ maxE) {
  int b = blockIdx.y;
  int i4 = blockIdx.x * blockDim.x + threadIdx.x;
  int N4 = N >> 2;
  if (i4 >= N4) return;
  int d1, d2, G; float mn0, mn1, mn2;
  get_dims(minE, maxE, b, vox, cap, d1, d2, G, mn0, mn1, mn2);
  const float* base = x + (size_t)b * 3 * N;
  float4 r0 = ((const float4*)base)[i4];
  float4 r1 = ((const float4*)(base + N))[i4];
  float4 r2 = ((const float4*)(base + 2 * (size_t)N))[i4];
  float4* cb = cells + (size_t)b * cellStride;
  const float px[4] = {r0.x, r0.y, r0.z, r0.w};
  const float py[4] = {r1.x, r1.y, r1.z, r1.w};
  const float pz[4] = {r2.x, r2.y, r2.z, r2.w};
#pragma unroll
  for (int k = 0; k < 4; ++k) {
    int v0 = (int)floorf(__fdiv_rn(__fsub_rn(px[k], mn0), vox));
    int v1 = (int)floorf(__fdiv_rn(__fsub_rn(py[k], mn1), vox));
    int v2 = (int)floorf(__fdiv_rn(__fsub_rn(pz[k], mn2), vox));
    int lin = (v0 * d1 + v1) * d2 + v2;
    if (lin < 0) lin = 0;
    if (lin > cap - 1) lin = cap - 1;  // safety only
    float4* c = &cb[lin];
    asm volatile("red.global.add.v4.f32 [%0], {%1, %2, %3, %4};"
                 :: "l"(c), "f"(px[k]), "f"(py[k]), "f"(pz[k]), "f"(1.0f)
                 : "memory");
  }
}

// ---- fused compaction: cluster of CH CTAs per batch.
// Each CTA stages its chunk in smem + counts it; cluster barrier; peer counts
// via DSMEM give the exclusive base; block-scan ordered write of centroids.
__global__ void __cluster_dims__(CH, 1, 1)
k_compact(const float4* __restrict__ cells, int cellStride, int cap,
          const unsigned* __restrict__ minE, const unsigned* __restrict__ maxE,
          float vox, float4* __restrict__ means, int* __restrict__ numvox) {
  int chunk = blockIdx.x;   // == cluster ctarank (cluster spans x)
  int b = blockIdx.y;
  int d1, d2, G; float mn0, mn1, mn2;
  get_dims(minE, maxE, b, vox, cap, d1, d2, G, mn0, mn1, mn2);
  int per = (G + CH - 1) / CH;
  int c0 = chunk * per;
  int n = min(per, G - c0); if (n < 0) n = 0;

  __shared__ float4 s_cells[PERMAX];
  __shared__ int s_cnt;            // this chunk's occupied count
  __shared__ int s_peer[CH];
  __shared__ int warpTot[8];

  int t = threadIdx.x, lane = t & 31, w = t >> 5;
  const float4* cb = cells + (size_t)b * cellStride;

  // stage + count
  int cnt = 0;
  for (int c = t; c < n; c += blockDim.x) {
    float4 v = cb[c0 + c];
    s_cells[c] = v;
    cnt += (v.w > 0.f);
  }
  int csum = cnt;
#pragma unroll
  for (int o = 16; o; o >>= 1) csum += __shfl_down_sync(0xffffffffu, csum, o);
  if (lane == 0) warpTot[w] = csum;
  __syncthreads();
  if (t == 0) {
    int tot = 0;
#pragma unroll
    for (int k = 0; k < 8; ++k) tot += warpTot[k];
    s_cnt = tot;
  }
  __syncthreads();

  // cluster barrier: counts visible cluster-wide
  asm volatile("barrier.cluster.arrive.aligned;" ::: "memory");
  asm volatile("barrier.cluster.wait.aligned;" ::: "memory");

  // gather peer counts (8 parallel DSMEM loads by warp 0)
  uint32_t cntAddr = smem_u32(&s_cnt);
  if (w == 0 && lane < CH) s_peer[lane] = dsmem_ld(cntAddr, (uint32_t)lane);
  __syncthreads();

  int base = 0;
#pragma unroll
  for (int r = 0; r < CH; ++r) base += (r < chunk) ? s_peer[r] : 0;
  if (chunk == 0 && t == 0) {
    int tot = 0;
#pragma unroll
    for (int r = 0; r < CH; ++r) tot += s_peer[r];
    numvox[b] = tot;
  }

  // ordered compaction from smem
  int ck = (n + (int)blockDim.x - 1) / (int)blockDim.x;
  int start = t * ck;
  int end = min(start + ck, n);
  int mycnt = 0;
  for (int c = start; c < end; ++c)
    if (s_cells[c].w > 0.f) mycnt++;

  int p = mycnt;
#pragma unroll
  for (int o = 1; o < 32; o <<= 1) {
    int v = __shfl_up_sync(0xffffffffu, p, o);
    if (lane >= o) p += v;
  }
  if (lane == 31) warpTot[w] = p;
  __syncthreads();
  int woff = 0;
  for (int k = 0; k < w; ++k) woff += warpTot[k];

  int off = base + woff + (p - mycnt);
  float4* mb = means + (size_t)b * cellStride;
  for (int c = start; c < end; ++c) {
    float4 s = s_cells[c];
    if (s.w > 0.f) {
      mb[off++] = make_float4(__fdiv_rn(s.x, s.w), __fdiv_rn(s.y, s.w),
                              __fdiv_rn(s.z, s.w), 0.f);
    }
  }
}

// partitionable threefry sampling, 4 samples/thread, float4 stores
template <bool TRACK>
__global__ void k_sample(float* __restrict__ out, int L, KeyArr keys,
                         const float4* __restrict__ means, int cellStride,
                         const int* __restrict__ numvox,
                         unsigned* __restrict__ minE2,
                         unsigned* __restrict__ maxE2) {
  int b = blockIdx.y;
  int i4 = blockIdx.x * blockDim.x + threadIdx.x;
  int L4 = L >> 2;
  unsigned mnE[3] = {0xFFFFFFFFu, 0xFFFFFFFFu, 0xFFFFFFFFu};
  unsigned mxE[3] = {0u, 0u, 0u};
  if (i4 < L4) {
    int nv = numvox[b];
    float fnv = __int2float_rn(nv);
    const float4* mb = means + (size_t)b * cellStride;
    float ox[4], oy[4], oz[4];
#pragma unroll
    for (int k = 0; k < 4; ++k) {
      unsigned i = (unsigned)(4 * i4 + k);
      unsigned o0, o1;
      threefry2x32(keys.a[b], keys.b[b], 0u, i, o0, o1);
      unsigned bits = o0 ^ o1;
      float u = __uint_as_float((bits >> 9) | 0x3F800000u) - 1.0f;
      float prod = __fmul_rn(u, fnv);
      int idx = (int)prod;             // trunc == astype(int32)
      if (idx > nv - 1) idx = nv - 1;
      float4 mv = mb[idx];
      ox[k] = mv.x; oy[k] = mv.y; oz[k] = mv.z;
      if (TRACK) {
        unsigned e;
        e = fenc(mv.x); mnE[0] = min(mnE[0], e); mxE[0] = max(mxE[0], e);
        e = fenc(mv.y); mnE[1] = min(mnE[1], e); mxE[1] = max(mxE[1], e);
        e = fenc(mv.z); mnE[2] = min(mnE[2], e); mxE[2] = max(mxE[2], e);
      }
    }
    size_t ob = (size_t)b * 3 * L;
    ((float4*)(out + ob))[i4]                   = make_float4(ox[0], ox[1], ox[2], ox[3]);
    ((float4*)(out + ob + L))[i4]               = make_float4(oy[0], oy[1], oy[2], oy[3]);
    ((float4*)(out + ob + 2 * (size_t)L))[i4]   = make_float4(oz[0], oz[1], oz[2], oz[3]);
  }
  if (TRACK) {
#pragma unroll
    for (int d = 0; d < 3; ++d) {
#pragma unroll
      for (int o = 16; o; o >>= 1) {
        mnE[d] = min(mnE[d], __shfl_down_sync(0xffffffffu, mnE[d], o));
        mxE[d] = max(mxE[d], __shfl_down_sync(0xffffffffu, mxE[d], o));
      }
    }
    __shared__ unsigned sm[6][8];
    int lane = threadIdx.x & 31, w = threadIdx.x >> 5;
    if (lane == 0) {
      sm[0][w] = mnE[0]; sm[1][w] = mxE[0]; sm[2][w] = mnE[1];
      sm[3][w] = mxE[1]; sm[4][w] = mnE[2]; sm[5][w] = mxE[2];
    }
    __syncthreads();
    if (threadIdx.x == 0) {
      unsigned a0 = 0xFFFFFFFFu, a1 = 0u, a2 = 0xFFFFFFFFu,
               a3 = 0u, a4 = 0xFFFFFFFFu, a5 = 0u;
      int nw = blockDim.x >> 5;
      for (int k = 0; k < nw; ++k) {
        a0 = min(a0, sm[0][k]); a1 = max(a1, sm[1][k]);
        a2 = min(a2, sm[2][k]); a3 = max(a3, sm[3][k]);
        a4 = min(a4, sm[4][k]); a5 = max(a5, sm[5][k]);
      }
      atomicMin(&minE2[b * 3 + 0], a0); atomicMax(&maxE2[b * 3 + 0], a1);
      atomicMin(&minE2[b * 3 + 1], a2); atomicMax(&maxE2[b * 3 + 1], a3);
      atomicMin(&minE2[b * 3 + 2], a4); atomicMax(&maxE2[b * 3 + 2], a5);
    }
  }
}

// ============================================================================
extern "C" void kernel_launch(void* const* d_in, const int* in_sizes, int n_in,
                              void* d_out, int out_size) {
  const float* x = (const float*)d_in[0];
  const int B = 16;
  const int N = in_sizes[0] / (B * 3);
  const int L1 = N / 2, L2 = N / 4;
  float* out1 = (float*)d_out;
  float* out2 = out1 + (size_t)B * 3 * L1;

  // JAX key derivation (partitionable): key(42) -> split 2 -> split 16
  unsigned k1a, k1b, k2a, k2b;
  threefry2x32(0u, 42u, 0u, 0u, k1a, k1b);
  threefry2x32(0u, 42u, 0u, 1u, k2a, k2b);
  KeyArr K1, K2;
  for (int b = 0; b < B; ++b) {
    threefry2x32(k1a, k1b, 0u, (unsigned)b, K1.a[b], K1.b[b]);
    threefry2x32(k2a, k2b, 0u, (unsigned)b, K2.a[b], K2.b[b]);
  }

  static float4 *cells1 = nullptr, *cells2, *means1, *means2;
  static int *numvox1, *numvox2;
  static unsigned *minE1, *maxE1, *minE2, *maxE2;
  if (!cells1) {
    cudaGetSymbolAddress((void**)&cells1, g_cells1);
    cudaGetSymbolAddress((void**)&cells2, g_cells2);
    cudaGetSymbolAddress((void**)&means1, g_means1);
    cudaGetSymbolAddress((void**)&means2, g_means2);
    cudaGetSymbolAddress((void**)&numvox1, g_numvox1);
    cudaGetSymbolAddress((void**)&numvox2, g_numvox2);
    cudaGetSymbolAddress((void**)&minE1, g_minEnc1);
    cudaGetSymbolAddress((void**)&maxE1, g_maxEnc1);
    cudaGetSymbolAddress((void**)&minE2, g_minEnc2);
    cudaGetSymbolAddress((void**)&maxE2, g_maxEnc2);
  }

  dim3 th(256);

  k_init<<<148, th>>>();

  // ---- layer 1: voxel 0.05
  k_minmax<<<dim3(16, B * 3), th>>>(x, N, minE1, maxE1);
  k_accum<<<dim3((N / 4 + 255) / 256, B), th>>>(x, N, 0.05f, cells1, GMAX, GMAX,
                                                minE1, maxE1);
  k_compact<<<dim3(CH, B), th>>>(cells1, GMAX, GMAX, minE1, maxE1, 0.05f,
                                 means1, numvox1);
  k_sample<true><<<dim3((L1 / 4 + 255) / 256, B), th>>>(out1, L1, K1, means1,
                                                        GMAX, numvox1, minE2, maxE2);

  // ---- layer 2: voxel 0.10 (min/max tracked by layer-1 sample)
  k_accum<<<dim3((L1 / 4 + 255) / 256, B), th>>>(out1, L1, 0.1f, cells2, GMAX2,
                                                 GMAX2, minE2, maxE2);
  k_compact<<<dim3(CH, B), th>>>(cells2, GMAX2, GMAX2, minE2, maxE2, 0.1f,
                                 means2, numvox2);
  k_sample<false><<<dim3((L2 / 4 + 255) / 256, B), th>>>(out2, L2, K2, means2,
                                                         GMAX2, numvox2,
                                                         nullptr, nullptr);
}